// round 7
// baseline (speedup 1.0000x reference)
#include <cuda_runtime.h>
#include <cuda_bf16.h>

// Soft-label distillation transform:
//   per row i: S = sum_j logits[i,j]; t = logits[i,label_i];
//   s = 0.95 / (1 + S - 2t)
//   out[i, j]     = s * logits[i,j]      (j != label)
//   out[i, label] = s*t + (1 - s*S)
//
// B=4096 rows, C=32000 cols, fp32 in/out.
// Labels buffer is int32: harness dtype set is f32/i32/bf16 (int64 is
// converted), and round-4's rel_err = sqrt(2) signature (correction
// landing on a wrong-but-valid index in every row) proved 8-byte reads
// were misindexing an int32 buffer.
//
// PERSISTENT design: grid = #SMs (1 CTA/SM, pinned by 128 KB smem), each
// CTA grid-strides over rows — removes ~27 wave transitions (~2360 cyc
// each). Row staged in SMEM so HBM sees exactly 1x read + 1x write
// (1.05 GB floor). __ldcs/__stcs: touched-once data, 512 MB >> 126 MB
// L2, so evict-first. SMEM crossbar traffic (~2000 cyc/row) and the
// per-row reduction bubble (~800 cyc) both sit well inside the per-row
// DRAM shadow (~6150 cyc), and bubbles across 148 unsynchronized CTAs
// are absorbed by the chip-wide DRAM limiter — pure HBM-bound kernel.

#define BATCH 4096
#define NUM_CLASSES 32000
#define NVEC (NUM_CLASSES / 4)   // 8000 float4 per row
#define NTHREADS 1024
#define ALPHA 0.95f

__global__ __launch_bounds__(NTHREADS, 1)
void distill_kernel(const float* __restrict__ logits,
                    const int* __restrict__ labels,
                    float* __restrict__ out)
{
    extern __shared__ float row[];                 // NUM_CLASSES floats = 128 KB
    __shared__ float warpsum[32];
    __shared__ float sS;

    const int tid  = threadIdx.x;
    float4* row4 = reinterpret_cast<float4*>(row);

    for (int b = blockIdx.x; b < BATCH; b += gridDim.x) {
        const float4* __restrict__ in4  =
            reinterpret_cast<const float4*>(logits) + (size_t)b * NVEC;
        float4* __restrict__ out4 =
            reinterpret_cast<float4*>(out) + (size_t)b * NVEC;

        // Pass 1: stream row from HBM -> SMEM, accumulate partial sum.
        float lsum = 0.0f;
        #pragma unroll 4
        for (int i = tid; i < NVEC; i += NTHREADS) {
            float4 v = __ldcs(&in4[i]);            // streaming load (read-once)
            row4[i] = v;
            lsum += (v.x + v.y) + (v.z + v.w);
        }

        // Block reduction of S.
        #pragma unroll
        for (int o = 16; o > 0; o >>= 1)
            lsum += __shfl_xor_sync(0xFFFFFFFFu, lsum, o);
        if ((tid & 31) == 0) warpsum[tid >> 5] = lsum;
        __syncthreads();
        if (tid < 32) {
            float v = warpsum[tid];
            #pragma unroll
            for (int o = 16; o > 0; o >>= 1)
                v += __shfl_xor_sync(0xFFFFFFFFu, v, o);
            if (tid == 0) sS = v;
        }
        __syncthreads();

        const float S     = sS;
        const int   label = labels[b];             // int32 (harness dtype)
        const float t     = row[label];            // broadcast LDS
        const float s     = ALPHA / (1.0f + S - 2.0f * t);
        const float corr  = 1.0f - s * S;
        const int   lvec  = label >> 2;            // float4 holding the label col
        const int   llane = label & 3;

        // Pass 2: scale from SMEM, inject correction at label, stream out.
        #pragma unroll 4
        for (int i = tid; i < NVEC; i += NTHREADS) {
            float4 v = row4[i];
            v.x *= s; v.y *= s; v.z *= s; v.w *= s;
            if (i == lvec) {                       // ISETP + @P FADD, DRAM-shadowed
                float* vf = reinterpret_cast<float*>(&v);
                vf[llane] += corr;
            }
            __stcs(&out4[i], v);                   // streaming store (write-once)
        }

        // Reuse smem buffer next row: all pass-2 reads must complete first.
        __syncthreads();
    }
}

extern "C" void kernel_launch(void* const* d_in, const int* in_sizes, int n_in,
                              void* d_out, int out_size)
{
    const float* logits = (const float*)d_in[0];
    const int*   labels = (const int*)d_in[1];
    float*       out    = (float*)d_out;

    const int smem_bytes = NUM_CLASSES * sizeof(float);   // 128000 B dynamic smem
    (void)cudaFuncSetAttribute(distill_kernel,
                               cudaFuncAttributeMaxDynamicSharedMemorySize,
                               smem_bytes);   // host-side, capture-legal

    // Persistent grid: exactly #SMs. Never more — at 1 CTA/SM occupancy a
    // surplus CTA would serialize behind an entire persistent loop.
    int dev = 0, nsm = 148;
    (void)cudaGetDevice(&dev);
    (void)cudaDeviceGetAttribute(&nsm, cudaDevAttrMultiProcessorCount, dev);
    int grid = nsm < BATCH ? nsm : BATCH;

    distill_kernel<<<grid, NTHREADS, smem_bytes>>>(logits, labels, out);
}

// round 8
// speedup vs baseline: 1.1460x; 1.1460x over previous
#include <cuda_runtime.h>
#include <cuda_bf16.h>

// Soft-label distillation transform:
//   per row i: S = sum_j logits[i,j]; t = logits[i,label_i];
//   s = 0.95 / (1 + S - 2t)
//   out[i, j]     = s * logits[i,j]      (j != label)
//   out[i, label] = s*t + (1 - s*S)
//
// B=4096 rows, C=32000 cols, fp32 in/out, labels int32.
//
// R7 measured: 184.4us, DRAM=67.2%. Gap vs floor = per-row bubble: the
// block reduction waited on the LAST LDG of the row (~1000cyc DRAM
// latency) + barriers, idling the load stream ~3.5Kcyc/row x 27 rows.
//
// R8: register prefetch pipeline. r[8] (float4, 32 regs) holds the NEXT
// row, loads issued a full row-time before consumption. Row b is staged
// regs->smem while summing FROM REGISTERS (no latency exposure), next
// row's LDGs issue before the reduction barriers + store phase, so the
// DRAM read stream never pauses at row boundaries.
//
// Persistent grid = #SMs (1 CTA/SM, 128KB smem pin). __ldcs/__stcs:
// touched-once data, 512MB >> 126MB L2. HBM sees exactly 1x read +
// 1x write (1.05 GB floor).

#define BATCH 4096
#define NUM_CLASSES 32000
#define NVEC (NUM_CLASSES / 4)   // 8000 float4 per row
#define NTHREADS 1024
#define ALPHA 0.95f

__global__ __launch_bounds__(NTHREADS, 1)
void distill_kernel(const float* __restrict__ logits,
                    const int* __restrict__ labels,
                    float* __restrict__ out)
{
    extern __shared__ float row[];                 // NUM_CLASSES floats = 128 KB
    __shared__ float warpsum[32];
    __shared__ float sS;

    const int  tid    = threadIdx.x;
    const bool lastok = (tid + 7 * NTHREADS) < NVEC;   // k=7 slot valid?
    float4* row4 = reinterpret_cast<float4*>(row);

    float4 r[8];                                   // prefetch buffer (next row)

    // Prologue: issue loads for this CTA's first row.
    {
        const float4* __restrict__ in4 =
            reinterpret_cast<const float4*>(logits) + (size_t)blockIdx.x * NVEC;
        #pragma unroll
        for (int k = 0; k < 7; k++) r[k] = __ldcs(&in4[tid + k * NTHREADS]);
        if (lastok)                r[7] = __ldcs(&in4[tid + 7 * NTHREADS]);
    }

    for (int b = blockIdx.x; b < BATCH; b += gridDim.x) {
        const int nb    = b + gridDim.x;
        const int label = labels[b];               // scalar, hidden under staging

        // Stage regs -> smem, summing from registers (loads issued one
        // full row earlier -> latency already absorbed).
        float lsum = 0.0f;
        #pragma unroll
        for (int k = 0; k < 7; k++) {
            float4 v = r[k];
            row4[tid + k * NTHREADS] = v;
            lsum += (v.x + v.y) + (v.z + v.w);
        }
        if (lastok) {
            float4 v = r[7];
            row4[tid + 7 * NTHREADS] = v;
            lsum += (v.x + v.y) + (v.z + v.w);
        }

        // Prefetch NEXT row now: these LDGs drain during the reduction
        // barriers and the entire store phase below (~5K cyc of cover).
        if (nb < BATCH) {
            const float4* __restrict__ nin4 =
                reinterpret_cast<const float4*>(logits) + (size_t)nb * NVEC;
            #pragma unroll
            for (int k = 0; k < 7; k++) r[k] = __ldcs(&nin4[tid + k * NTHREADS]);
            if (lastok)                r[7] = __ldcs(&nin4[tid + 7 * NTHREADS]);
        }

        // Block reduction of S.
        #pragma unroll
        for (int o = 16; o > 0; o >>= 1)
            lsum += __shfl_xor_sync(0xFFFFFFFFu, lsum, o);
        if ((tid & 31) == 0) warpsum[tid >> 5] = lsum;
        __syncthreads();                           // row4 + warpsum visible
        if (tid < 32) {
            float v = warpsum[tid];
            #pragma unroll
            for (int o = 16; o > 0; o >>= 1)
                v += __shfl_xor_sync(0xFFFFFFFFu, v, o);
            if (tid == 0) sS = v;
        }
        __syncthreads();

        const float S     = sS;
        const float t     = row[label];            // broadcast LDS
        const float s     = ALPHA / (1.0f + S - 2.0f * t);
        const float corr  = 1.0f - s * S;
        const int   lvec  = label >> 2;
        const int   llane = label & 3;

        // Store phase: read smem, scale, patch label, stream out.
        float4* __restrict__ out4 =
            reinterpret_cast<float4*>(out) + (size_t)b * NVEC;
        #pragma unroll 4
        for (int i = tid; i < NVEC; i += NTHREADS) {
            float4 v = row4[i];
            v.x *= s; v.y *= s; v.z *= s; v.w *= s;
            if (i == lvec) {                       // ISETP + @P FADD
                float* vf = reinterpret_cast<float*>(&v);
                vf[llane] += corr;
            }
            __stcs(&out4[i], v);
        }

        // All smem reads done before next iteration's STS overwrites row4.
        __syncthreads();
    }
}

extern "C" void kernel_launch(void* const* d_in, const int* in_sizes, int n_in,
                              void* d_out, int out_size)
{
    const float* logits = (const float*)d_in[0];
    const int*   labels = (const int*)d_in[1];
    float*       out    = (float*)d_out;

    const int smem_bytes = NUM_CLASSES * sizeof(float);   // 128000 B dynamic smem
    (void)cudaFuncSetAttribute(distill_kernel,
                               cudaFuncAttributeMaxDynamicSharedMemorySize,
                               smem_bytes);

    // Persistent grid: exactly #SMs (152 on GB300). Never more — at
    // 1 CTA/SM occupancy a surplus CTA would serialize behind a full loop.
    int dev = 0, nsm = 148;
    (void)cudaGetDevice(&dev);
    (void)cudaDeviceGetAttribute(&nsm, cudaDevAttrMultiProcessorCount, dev);
    int grid = nsm < BATCH ? nsm : BATCH;

    distill_kernel<<<grid, NTHREADS, smem_bytes>>>(logits, labels, out);
}